// round 5
// baseline (speedup 1.0000x reference)
#include <cuda_runtime.h>
#include <cuda_bf16.h>
#include <cstdint>

#define D_FEAT    128
#define OUT_DIM   128
#define MAX_NODES 100000
#define MAX_EDGES 600000
#define SCAN_BLK  1024
#define CNT_PAD   102400     // padded for int4 scan loads

// GEMM tile: 128 rows x 256 cols, K = 128
#define TM   128
#define TN   256
#define LDA  136             // padded bf16 row (272 B stride)
#define GT   256             // 8 warps

// ---- device scratch (allocation-free) ----
__device__ float g_y1[(size_t)MAX_NODES * D_FEAT];   // x @ W[:128]
__device__ float g_y2[(size_t)MAX_NODES * D_FEAT];   // x @ W[128:]
__device__ __align__(16) int g_cnt[CNT_PAD];
__device__ int   g_off[MAX_NODES + 1];
__device__ int   g_cur[MAX_NODES];
__device__ int   g_bsum[128];
__device__ int2  g_edge[MAX_EDGES];
// bf16 hi/lo image of Wcat^T: [part][j=0..255][k padded to LDA]
__device__ uint4 g_Bimg4[8704];   // 139264 B

// ============================ PTX helpers =================================
__device__ __forceinline__ uint32_t smem_u32(const void* p) {
    uint32_t a;
    asm("{ .reg .u64 t; cvta.to.shared.u64 t, %1; cvt.u32.u64 %0, t; }" : "=r"(a) : "l"(p));
    return a;
}
__device__ __forceinline__ void ldsm4(uint32_t* r, uint32_t addr) {
    asm volatile("ldmatrix.sync.aligned.m8n8.x4.shared.b16 {%0,%1,%2,%3}, [%4];"
                 : "=r"(r[0]), "=r"(r[1]), "=r"(r[2]), "=r"(r[3]) : "r"(addr));
}
__device__ __forceinline__ void mma_bf16(float* d, const uint32_t* a,
                                         uint32_t b0, uint32_t b1) {
    asm volatile(
        "mma.sync.aligned.m16n8k16.row.col.f32.bf16.bf16.f32 "
        "{%0,%1,%2,%3}, {%4,%5,%6,%7}, {%8,%9}, {%0,%1,%2,%3};"
        : "+f"(d[0]), "+f"(d[1]), "+f"(d[2]), "+f"(d[3])
        : "r"(a[0]), "r"(a[1]), "r"(a[2]), "r"(a[3]), "r"(b0), "r"(b1));
}
__device__ __forceinline__ uint32_t bf16x2(float y, float x) {
    uint32_t r; asm("cvt.rn.bf16x2.f32 %0, %1, %2;" : "=r"(r) : "f"(y), "f"(x)); return r;
}

// ================= fused prep: zero counts + build B image =================
// Wcat[k][j] = (j<128) ? W[k][j] : W[k+128][j-128],  k in [0,128), j in [0,256)
__global__ void prep_kernel(const float* __restrict__ W, int n, int n_edges) {
    int i = blockIdx.x * blockDim.x + threadIdx.x;
    if (i < CNT_PAD) g_cnt[i] = 0;
    if (i == 0) g_off[n] = n_edges;
    if (i < 256 * 128) {
        int j = i >> 7;          // 0..255
        int k = i & 127;
        float w = (j < 128) ? W[(size_t)k * OUT_DIM + j]
                            : W[(size_t)(k + 128) * OUT_DIM + (j - 128)];
        __nv_bfloat16 hb = __float2bfloat16(w);
        __nv_bfloat16 lb = __float2bfloat16(w - __bfloat162float(hb));
        __nv_bfloat16* img = (__nv_bfloat16*)g_Bimg4;
        img[((size_t)0 * 256 + j) * LDA + k] = hb;
        img[((size_t)1 * 256 + j) * LDA + k] = lb;
    }
}

// ========================= CSR build kernels ===============================
__global__ void hist_kernel(const int* __restrict__ rows, int n_edges) {
    int i = blockIdx.x * blockDim.x + threadIdx.x;
    if (i < n_edges) atomicAdd(&g_cnt[rows[i]], 1);
}

// per-1024-element block totals (256 threads, int4 + shuffle)
__global__ void scan_reduce_kernel(int n) {
    __shared__ int ws[8];
    int t = threadIdx.x;
    int4 v = ((const int4*)g_cnt)[blockIdx.x * 256 + t];   // pad region is zero
    int s = v.x + v.y + v.z + v.w;
#pragma unroll
    for (int o = 16; o > 0; o >>= 1) s += __shfl_xor_sync(~0u, s, o);
    if ((t & 31) == 0) ws[t >> 5] = s;
    __syncthreads();
    if (t < 8) {
        s = ws[t];
#pragma unroll
        for (int o = 4; o > 0; o >>= 1) s += __shfl_xor_sync(0xffu, s, o);
        if (t == 0) g_bsum[blockIdx.x] = s;
    }
}

// fused block-base + shuffle exclusive scan; writes offsets + cursors
__global__ void scan_write_kernel(int n, int nb) {
    __shared__ int wsum[32];
    __shared__ int sbase;
    int t = threadIdx.x, lane = t & 31, w = t >> 5;

    if (w == 0) {
        int lim = min((int)blockIdx.x, nb);
        int b = 0;
        for (int j = lane; j < lim; j += 32) b += g_bsum[j];
#pragma unroll
        for (int o = 16; o > 0; o >>= 1) b += __shfl_xor_sync(~0u, b, o);
        if (lane == 0) sbase = b;
    }

    int i = blockIdx.x * SCAN_BLK + t;
    int v = (i < n) ? g_cnt[i] : 0;
    int s = v;
#pragma unroll
    for (int d = 1; d < 32; d <<= 1) {
        int q = __shfl_up_sync(~0u, s, d);
        if (lane >= d) s += q;
    }
    if (lane == 31) wsum[w] = s;
    __syncthreads();
    if (w == 0) {
        int q = wsum[lane];
#pragma unroll
        for (int d = 1; d < 32; d <<= 1) {
            int r = __shfl_up_sync(~0u, q, d);
            if (lane >= d) q += r;
        }
        wsum[lane] = q;
    }
    __syncthreads();
    if (i < n) {
        int wbase = (w > 0) ? wsum[w - 1] : 0;
        int o = sbase + wbase + s - v;
        g_off[i] = o;
        g_cur[i] = o;
    }
}

__global__ void scatter_kernel(const int* __restrict__ rows,
                               const int* __restrict__ cols,
                               const float* __restrict__ vals,
                               int n_edges) {
    int i = blockIdx.x * blockDim.x + threadIdx.x;
    if (i < n_edges) {
        int r = rows[i];
        int p = atomicAdd(&g_cur[r], 1);
        g_edge[p] = make_int2(cols[i], __float_as_int(vals[i]));
    }
}

// ==== GEMM: y = x @ Wcat  (bf16 3-pass, mma.sync), y1 | y2 split outputs ====
// smem: A hi [128][LDA] (34816 B) | A lo (34816) | B hi [256][LDA] (69632) | B lo
#define SM_A       0
#define SM_PART_A  34816
#define SM_B       69632
#define SM_PART_B  69632
#define SM_TOTAL   208896

__global__ __launch_bounds__(GT, 1)
void gemm_mma_kernel(const float* __restrict__ x, int n_nodes) {
    extern __shared__ char smem[];
    const uint32_t sbase = smem_u32(smem);
    const int tid  = threadIdx.x;
    const int wid  = tid >> 5;
    const int lane = tid & 31;
    const int wm   = wid >> 1;       // 0..3 : 32-row strip
    const int wn   = wid & 1;        // 0..1 : y1 (cols 0-127) or y2
    const int row0 = blockIdx.x * TM;

    uint32_t pA[2], pB[8];
#pragma unroll
    for (int mf = 0; mf < 2; mf++)
        pA[mf] = sbase + SM_A
               + (uint32_t)((wm * 32 + mf * 16 + (lane & 15)) * (LDA * 2))
               + (uint32_t)((lane >> 4) << 4);
#pragma unroll
    for (int p = 0; p < 8; p++)
        pB[p] = sbase + SM_B
              + (uint32_t)((wn * 128 + p * 16 + (lane & 7) + ((lane >> 4) << 3)) * (LDA * 2))
              + (uint32_t)((lane & 8) << 1);

    // ---- stage A: split x rows fp32 -> bf16 hi/lo ----
#pragma unroll
    for (int j = 0; j < (TM * 128 / 4) / GT; j++) {      // 16 iters
        int i  = tid + j * GT;
        int r  = i >> 5;
        int kq = i & 31;
        int gr = row0 + r;
        float4 v = make_float4(0.f, 0.f, 0.f, 0.f);
        if (gr < n_nodes) v = ((const float4*)(x + (size_t)gr * D_FEAT))[kq];
        uint32_t h01 = bf16x2(v.y, v.x);
        uint32_t h23 = bf16x2(v.w, v.z);
        float fx = __uint_as_float(h01 << 16);
        float fy = __uint_as_float(h01 & 0xffff0000u);
        float fz = __uint_as_float(h23 << 16);
        float fw = __uint_as_float(h23 & 0xffff0000u);
        uint32_t l01 = bf16x2(v.y - fy, v.x - fx);
        uint32_t l23 = bf16x2(v.w - fw, v.z - fz);
        char* dst = smem + SM_A + r * (LDA * 2) + kq * 8;
        *(uint2*)dst              = make_uint2(h01, h23);
        *(uint2*)(dst + SM_PART_A) = make_uint2(l01, l23);
    }
    // ---- copy prebuilt B image (hi+lo, 139264 B) ----
    {
        uint4* dB = (uint4*)(smem + SM_B);
#pragma unroll
        for (int j = tid; j < 8704; j += GT) dB[j] = g_Bimg4[j];
    }
    __syncthreads();

    float acc[2][8][8];
#pragma unroll
    for (int mf = 0; mf < 2; mf++)
#pragma unroll
        for (int p = 0; p < 8; p++)
#pragma unroll
            for (int q = 0; q < 8; q++) acc[mf][p][q] = 0.f;

    // ---- mainloop: 8 k-steps of 16 ----
#pragma unroll
    for (int ks = 0; ks < 8; ks++) {
        const uint32_t k0b = (uint32_t)(ks << 5);
        uint32_t Ah[2][4], Al[2][4];
#pragma unroll
        for (int mf = 0; mf < 2; mf++) {
            ldsm4(Ah[mf], pA[mf] + k0b);
            ldsm4(Al[mf], pA[mf] + SM_PART_A + k0b);
        }
#pragma unroll
        for (int p = 0; p < 8; p++) {
            uint32_t Bh[4], Bl[4];
            ldsm4(Bh, pB[p] + k0b);
            ldsm4(Bl, pB[p] + SM_PART_B + k0b);
#pragma unroll
            for (int mf = 0; mf < 2; mf++) {
                float* a = acc[mf][p];
                mma_bf16(a,     Ah[mf], Bh[0], Bh[1]);
                mma_bf16(a + 4, Ah[mf], Bh[2], Bh[3]);
                mma_bf16(a,     Al[mf], Bh[0], Bh[1]);
                mma_bf16(a + 4, Al[mf], Bh[2], Bh[3]);
                mma_bf16(a,     Ah[mf], Bl[0], Bl[1]);
                mma_bf16(a + 4, Ah[mf], Bl[2], Bl[3]);
            }
        }
    }

    // ---- store y fragments (no relu here) ----
    float* dst = wn ? g_y2 : g_y1;
#pragma unroll
    for (int mf = 0; mf < 2; mf++) {
        int r0 = row0 + wm * 32 + mf * 16 + (lane >> 2);
        int r1 = r0 + 8;
#pragma unroll
        for (int p = 0; p < 8; p++) {
            int c0 = p * 16 + (lane & 3) * 2;
            float* a = acc[mf][p];
            if (r0 < n_nodes) {
                *(float2*)(dst + (size_t)r0 * D_FEAT + c0)     = make_float2(a[0], a[1]);
                *(float2*)(dst + (size_t)r0 * D_FEAT + c0 + 8) = make_float2(a[4], a[5]);
            }
            if (r1 < n_nodes) {
                *(float2*)(dst + (size_t)r1 * D_FEAT + c0)     = make_float2(a[2], a[3]);
                *(float2*)(dst + (size_t)r1 * D_FEAT + c0 + 8) = make_float2(a[6], a[7]);
            }
        }
    }
}

// ===== final fused SpMM: out[r] = relu( sum val*y1[col]  +  y2[r] ) ========
__global__ void spmm_out_kernel(float* __restrict__ out, int n_nodes) {
    int row  = (blockIdx.x * blockDim.x + threadIdx.x) >> 5;
    int lane = threadIdx.x & 31;
    if (row >= n_nodes) return;

    int e  = g_off[row];
    int e1 = g_off[row + 1];

    float4 a0 = make_float4(0.f, 0.f, 0.f, 0.f);
    float4 a1 = make_float4(0.f, 0.f, 0.f, 0.f);
    for (; e + 2 <= e1; e += 2) {
        int2 ev0 = g_edge[e];
        int2 ev1 = g_edge[e + 1];
        float4 x0 = ((const float4*)(g_y1 + (size_t)ev0.x * D_FEAT))[lane];
        float4 x1 = ((const float4*)(g_y1 + (size_t)ev1.x * D_FEAT))[lane];
        float v0 = __int_as_float(ev0.y);
        float v1 = __int_as_float(ev1.y);
        a0.x = fmaf(v0, x0.x, a0.x); a0.y = fmaf(v0, x0.y, a0.y);
        a0.z = fmaf(v0, x0.z, a0.z); a0.w = fmaf(v0, x0.w, a0.w);
        a1.x = fmaf(v1, x1.x, a1.x); a1.y = fmaf(v1, x1.y, a1.y);
        a1.z = fmaf(v1, x1.z, a1.z); a1.w = fmaf(v1, x1.w, a1.w);
    }
    if (e < e1) {
        int2 ev = g_edge[e];
        float4 xv = ((const float4*)(g_y1 + (size_t)ev.x * D_FEAT))[lane];
        float v = __int_as_float(ev.y);
        a0.x = fmaf(v, xv.x, a0.x); a0.y = fmaf(v, xv.y, a0.y);
        a0.z = fmaf(v, xv.z, a0.z); a0.w = fmaf(v, xv.w, a0.w);
    }
    float4 b = ((const float4*)(g_y2 + (size_t)row * D_FEAT))[lane];
    float4 o;
    o.x = fmaxf(a0.x + a1.x + b.x, 0.f);
    o.y = fmaxf(a0.y + a1.y + b.y, 0.f);
    o.z = fmaxf(a0.z + a1.z + b.z, 0.f);
    o.w = fmaxf(a0.w + a1.w + b.w, 0.f);
    ((float4*)(out + (size_t)row * D_FEAT))[lane] = o;
}

// ============================== launch =====================================
extern "C" void kernel_launch(void* const* d_in, const int* in_sizes, int n_in,
                              void* d_out, int out_size) {
    const float* x    = (const float*)d_in[0];
    const int*   rows = (const int*)  d_in[1];
    const int*   cols = (const int*)  d_in[2];
    const float* vals = (const float*)d_in[3];
    const float* W    = (const float*)d_in[4];
    float*       out  = (float*)d_out;

    const int n_nodes = in_sizes[0] / D_FEAT;
    const int n_edges = in_sizes[1];
    const int nb      = (n_nodes + SCAN_BLK - 1) / SCAN_BLK;

    // prep: zero counts + B image
    prep_kernel<<<(CNT_PAD + 255) / 256, 256>>>(W, n_nodes, n_edges);

    // dense GEMM y = x @ [W1|W2]  (independent of graph structure)
    cudaFuncSetAttribute(gemm_mma_kernel,
                         cudaFuncAttributeMaxDynamicSharedMemorySize, SM_TOTAL);
    gemm_mma_kernel<<<(n_nodes + TM - 1) / TM, GT, SM_TOTAL>>>(x, n_nodes);

    // CSR build
    hist_kernel<<<(n_edges + 255) / 256, 256>>>(rows, n_edges);
    scan_reduce_kernel<<<nb, 256>>>(n_nodes);
    scan_write_kernel<<<nb, SCAN_BLK>>>(n_nodes, nb);
    scatter_kernel<<<(n_edges + 255) / 256, 256>>>(rows, cols, vals, n_edges);

    // fused aggregate + bias + relu
    long long spmm_threads = (long long)n_nodes * 32;
    spmm_out_kernel<<<(int)((spmm_threads + 255) / 256), 256>>>(out, n_nodes);
}

// round 6
// speedup vs baseline: 1.0361x; 1.0361x over previous
#include <cuda_runtime.h>
#include <cuda_bf16.h>
#include <cstdint>

#define D_FEAT    128
#define OUT_DIM   128
#define MAX_NODES 100000
#define MAX_EDGES 600000
#define SCAN_BLK  1024
#define CNT_PAD   102400

#define TM   128          // rows per block tile
#define LDA  136          // padded bf16 row (272 B stride)
#define FT   512          // fused kernel threads (16 warps)

// ---- device scratch (allocation-free) ----
__device__ __align__(16) int g_cnt[CNT_PAD];
__device__ int   g_off[MAX_NODES + 1];
__device__ int   g_cur[MAX_NODES];
__device__ int   g_bsum[128];
__device__ int2  g_edge[MAX_EDGES];
// bf16 hi/lo images of B chunks: [chunk][part][n=128][k padded to LDA]
__device__ uint4 g_Bimg4[2 * 4352];   // 2 x 69632 B

// ============================ PTX helpers =================================
__device__ __forceinline__ uint32_t smem_u32(const void* p) {
    uint32_t a;
    asm("{ .reg .u64 t; cvta.to.shared.u64 t, %1; cvt.u32.u64 %0, t; }" : "=r"(a) : "l"(p));
    return a;
}
__device__ __forceinline__ void ldsm4(uint32_t* r, uint32_t addr) {
    asm volatile("ldmatrix.sync.aligned.m8n8.x4.shared.b16 {%0,%1,%2,%3}, [%4];"
                 : "=r"(r[0]), "=r"(r[1]), "=r"(r[2]), "=r"(r[3]) : "r"(addr));
}
__device__ __forceinline__ void mma_bf16(float* d, const uint32_t* a,
                                         uint32_t b0, uint32_t b1) {
    asm volatile(
        "mma.sync.aligned.m16n8k16.row.col.f32.bf16.bf16.f32 "
        "{%0,%1,%2,%3}, {%4,%5,%6,%7}, {%8,%9}, {%0,%1,%2,%3};"
        : "+f"(d[0]), "+f"(d[1]), "+f"(d[2]), "+f"(d[3])
        : "r"(a[0]), "r"(a[1]), "r"(a[2]), "r"(a[3]), "r"(b0), "r"(b1));
}
__device__ __forceinline__ uint32_t bf16x2(float y, float x) {
    uint32_t r; asm("cvt.rn.bf16x2.f32 %0, %1, %2;" : "=r"(r) : "f"(y), "f"(x)); return r;
}

// ================= prep: zero counts + build B images ======================
__global__ void prep_kernel(const float* __restrict__ W, int n, int n_edges) {
    int i = blockIdx.x * blockDim.x + threadIdx.x;
    if (i < CNT_PAD) g_cnt[i] = 0;
    if (i == 0) g_off[n] = n_edges;
    if (i < 2 * 128 * 128) {
        int c = i >> 14;
        int r = i & 16383;
        int k = r >> 7;
        int nn = r & 127;
        float w = W[(size_t)(c * 128 + k) * OUT_DIM + nn];
        __nv_bfloat16 hb = __float2bfloat16(w);
        __nv_bfloat16 lb = __float2bfloat16(w - __bfloat162float(hb));
        __nv_bfloat16* img = (__nv_bfloat16*)g_Bimg4;
        img[(((size_t)c * 2 + 0) * 128 + nn) * LDA + k] = hb;
        img[(((size_t)c * 2 + 1) * 128 + nn) * LDA + k] = lb;
    }
}

// ========================= CSR build kernels ===============================
__global__ void hist_kernel(const int* __restrict__ rows, int n_edges) {
    int i = blockIdx.x * blockDim.x + threadIdx.x;
    if (i < n_edges) atomicAdd(&g_cnt[rows[i]], 1);
}

__global__ void scan_reduce_kernel(int n) {
    __shared__ int ws[8];
    int t = threadIdx.x;
    int4 v = ((const int4*)g_cnt)[blockIdx.x * 256 + t];
    int s = v.x + v.y + v.z + v.w;
#pragma unroll
    for (int o = 16; o > 0; o >>= 1) s += __shfl_xor_sync(~0u, s, o);
    if ((t & 31) == 0) ws[t >> 5] = s;
    __syncthreads();
    if (t < 8) {
        s = ws[t];
#pragma unroll
        for (int o = 4; o > 0; o >>= 1) s += __shfl_xor_sync(0xffu, s, o);
        if (t == 0) g_bsum[blockIdx.x] = s;
    }
}

__global__ void scan_write_kernel(int n, int nb) {
    __shared__ int wsum[32];
    __shared__ int sbase;
    int t = threadIdx.x, lane = t & 31, w = t >> 5;

    if (w == 0) {
        int lim = min((int)blockIdx.x, nb);
        int b = 0;
        for (int j = lane; j < lim; j += 32) b += g_bsum[j];
#pragma unroll
        for (int o = 16; o > 0; o >>= 1) b += __shfl_xor_sync(~0u, b, o);
        if (lane == 0) sbase = b;
    }

    int i = blockIdx.x * SCAN_BLK + t;
    int v = (i < n) ? g_cnt[i] : 0;
    int s = v;
#pragma unroll
    for (int d = 1; d < 32; d <<= 1) {
        int q = __shfl_up_sync(~0u, s, d);
        if (lane >= d) s += q;
    }
    if (lane == 31) wsum[w] = s;
    __syncthreads();
    if (w == 0) {
        int q = wsum[lane];
#pragma unroll
        for (int d = 1; d < 32; d <<= 1) {
            int r = __shfl_up_sync(~0u, q, d);
            if (lane >= d) q += r;
        }
        wsum[lane] = q;
    }
    __syncthreads();
    if (i < n) {
        int wbase = (w > 0) ? wsum[w - 1] : 0;
        int o = sbase + wbase + s - v;
        g_off[i] = o;
        g_cur[i] = o;
    }
}

__global__ void scatter_kernel(const int* __restrict__ rows,
                               const int* __restrict__ cols,
                               const float* __restrict__ vals,
                               int n_edges) {
    int i = blockIdx.x * blockDim.x + threadIdx.x;
    if (i < n_edges) {
        int r = rows[i];
        int p = atomicAdd(&g_cur[r], 1);
        g_edge[p] = make_int2(cols[i], __float_as_int(vals[i]));
    }
}

// ===== fused kernel: h-tile SpMM (smem) -> 3-pass bf16 MMA -> relu out =====
// smem: A hi [128][LDA] (34816) | A lo (34816) | B hi (34816) | B lo (34816)
#define SM_A     0
#define SM_PART  34816
#define SM_B     69632
#define SM_TOTAL 139264

__global__ __launch_bounds__(FT, 1)
void fused_kernel(const float* __restrict__ x,
                  float* __restrict__ out,
                  int n_nodes) {
    extern __shared__ char smem[];
    const uint32_t sbase = smem_u32(smem);
    const int tid  = threadIdx.x;
    const int wid  = tid >> 5;
    const int lane = tid & 31;
    const int wm   = wid >> 2;      // 0..3  (32-row strip)
    const int wn   = wid & 3;       // 0..3  (32-col strip)
    const int row0 = blockIdx.x * TM;

    // ldmatrix base pointers
    uint32_t pA[2], pB[2];
#pragma unroll
    for (int mf = 0; mf < 2; mf++)
        pA[mf] = sbase + SM_A
               + (uint32_t)((wm * 32 + mf * 16 + (lane & 15)) * (LDA * 2))
               + (uint32_t)((lane >> 4) << 4);
#pragma unroll
    for (int p = 0; p < 2; p++)
        pB[p] = sbase + SM_B
              + (uint32_t)((wn * 32 + p * 16 + (lane & 7) + ((lane >> 4) << 3)) * (LDA * 2))
              + (uint32_t)((lane & 8) << 1);

    // ---- copy B chunk 0 image ----
    {
        uint4* dB = (uint4*)(smem + SM_B);
        for (int j = tid; j < 4352; j += FT) dB[j] = g_Bimg4[j];
    }

    // ---- SpMM phase: compute h rows, write bf16 hi/lo straight to A image --
#pragma unroll 1
    for (int rr = 0; rr < TM / 16; rr++) {          // 8 rows per warp
        int r  = wid * (TM / 16) + rr;
        int gr = row0 + r;
        float4 aA = make_float4(0.f, 0.f, 0.f, 0.f);
        float4 aB = make_float4(0.f, 0.f, 0.f, 0.f);
        if (gr < n_nodes) {
            int e  = g_off[gr];
            int e1 = g_off[gr + 1];
            for (; e + 4 <= e1; e += 4) {
                int2 e0 = g_edge[e],     e1v = g_edge[e + 1];
                int2 e2 = g_edge[e + 2], e3v = g_edge[e + 3];
                float4 x0 = ((const float4*)(x + (size_t)e0.x  * D_FEAT))[lane];
                float4 x1 = ((const float4*)(x + (size_t)e1v.x * D_FEAT))[lane];
                float4 x2 = ((const float4*)(x + (size_t)e2.x  * D_FEAT))[lane];
                float4 x3 = ((const float4*)(x + (size_t)e3v.x * D_FEAT))[lane];
                float v0 = __int_as_float(e0.y),  v1 = __int_as_float(e1v.y);
                float v2 = __int_as_float(e2.y),  v3 = __int_as_float(e3v.y);
                aA.x = fmaf(v0, x0.x, aA.x); aA.y = fmaf(v0, x0.y, aA.y);
                aA.z = fmaf(v0, x0.z, aA.z); aA.w = fmaf(v0, x0.w, aA.w);
                aB.x = fmaf(v1, x1.x, aB.x); aB.y = fmaf(v1, x1.y, aB.y);
                aB.z = fmaf(v1, x1.z, aB.z); aB.w = fmaf(v1, x1.w, aB.w);
                aA.x = fmaf(v2, x2.x, aA.x); aA.y = fmaf(v2, x2.y, aA.y);
                aA.z = fmaf(v2, x2.z, aA.z); aA.w = fmaf(v2, x2.w, aA.w);
                aB.x = fmaf(v3, x3.x, aB.x); aB.y = fmaf(v3, x3.y, aB.y);
                aB.z = fmaf(v3, x3.z, aB.z); aB.w = fmaf(v3, x3.w, aB.w);
            }
            for (; e < e1; e++) {
                int2 ev = g_edge[e];
                float4 xv = ((const float4*)(x + (size_t)ev.x * D_FEAT))[lane];
                float v = __int_as_float(ev.y);
                aA.x = fmaf(v, xv.x, aA.x); aA.y = fmaf(v, xv.y, aA.y);
                aA.z = fmaf(v, xv.z, aA.z); aA.w = fmaf(v, xv.w, aA.w);
            }
        }
        float4 hv = make_float4(aA.x + aB.x, aA.y + aB.y, aA.z + aB.z, aA.w + aB.w);
        // fp32 -> bf16 hi/lo, store into A image at [r][lane*4..+3]
        uint32_t h01 = bf16x2(hv.y, hv.x);
        uint32_t h23 = bf16x2(hv.w, hv.z);
        float fx = __uint_as_float(h01 << 16);
        float fy = __uint_as_float(h01 & 0xffff0000u);
        float fz = __uint_as_float(h23 << 16);
        float fw = __uint_as_float(h23 & 0xffff0000u);
        uint32_t l01 = bf16x2(hv.y - fy, hv.x - fx);
        uint32_t l23 = bf16x2(hv.w - fw, hv.z - fz);
        char* dst = smem + SM_A + r * (LDA * 2) + lane * 8;
        *(uint2*)dst             = make_uint2(h01, h23);
        *(uint2*)(dst + SM_PART) = make_uint2(l01, l23);
    }
    __syncthreads();

    float acc[2][4][4];
#pragma unroll
    for (int mf = 0; mf < 2; mf++)
#pragma unroll
        for (int nf = 0; nf < 4; nf++)
#pragma unroll
            for (int q = 0; q < 4; q++) acc[mf][nf][q] = 0.f;

    // ---- MMA over 2 chunks (chunk 0: h image in place; chunk 1: x) ----
    for (int c = 0; c < 2; c++) {
        if (c == 1) {
            __syncthreads();   // protect A/B images before restage
            // stage A = x rows (split fp32 -> bf16 hi/lo)
#pragma unroll
            for (int j = 0; j < (TM * 128 / 4) / FT; j++) {   // 8 iters
                int i  = tid + j * FT;
                int r  = i >> 5;
                int kq = i & 31;
                int gr = row0 + r;
                float4 v = make_float4(0.f, 0.f, 0.f, 0.f);
                if (gr < n_nodes) v = ((const float4*)(x + (size_t)gr * D_FEAT))[kq];
                uint32_t h01 = bf16x2(v.y, v.x);
                uint32_t h23 = bf16x2(v.w, v.z);
                float fx = __uint_as_float(h01 << 16);
                float fy = __uint_as_float(h01 & 0xffff0000u);
                float fz = __uint_as_float(h23 << 16);
                float fw = __uint_as_float(h23 & 0xffff0000u);
                uint32_t l01 = bf16x2(v.y - fy, v.x - fx);
                uint32_t l23 = bf16x2(v.w - fw, v.z - fz);
                char* dst = smem + SM_A + r * (LDA * 2) + kq * 8;
                *(uint2*)dst             = make_uint2(h01, h23);
                *(uint2*)(dst + SM_PART) = make_uint2(l01, l23);
            }
            // copy B chunk 1 image
            uint4* dB = (uint4*)(smem + SM_B);
            for (int j = tid; j < 4352; j += FT) dB[j] = g_Bimg4[4352 + j];
            __syncthreads();
        }

#pragma unroll
        for (int ks = 0; ks < 8; ks++) {
            const uint32_t k0b = (uint32_t)(ks << 5);
            uint32_t Ah[2][4], Al[2][4];
#pragma unroll
            for (int mf = 0; mf < 2; mf++) {
                ldsm4(Ah[mf], pA[mf] + k0b);
                ldsm4(Al[mf], pA[mf] + SM_PART + k0b);
            }
#pragma unroll
            for (int p = 0; p < 2; p++) {
                uint32_t Bh[4], Bl[4];
                ldsm4(Bh, pB[p] + k0b);
                ldsm4(Bl, pB[p] + SM_PART + k0b);
#pragma unroll
                for (int mf = 0; mf < 2; mf++) {
                    float* a0 = acc[mf][2 * p];
                    float* a1 = acc[mf][2 * p + 1];
                    mma_bf16(a0, Ah[mf], Bh[0], Bh[1]);
                    mma_bf16(a1, Ah[mf], Bh[2], Bh[3]);
                    mma_bf16(a0, Al[mf], Bh[0], Bh[1]);
                    mma_bf16(a1, Al[mf], Bh[2], Bh[3]);
                    mma_bf16(a0, Ah[mf], Bl[0], Bl[1]);
                    mma_bf16(a1, Ah[mf], Bl[2], Bl[3]);
                }
            }
        }
    }

    // ---- epilogue: relu + store ----
#pragma unroll
    for (int mf = 0; mf < 2; mf++) {
        int r0 = row0 + wm * 32 + mf * 16 + (lane >> 2);
        int r1 = r0 + 8;
#pragma unroll
        for (int nf = 0; nf < 4; nf++) {
            int col = wn * 32 + nf * 8 + (lane & 3) * 2;
            float* a = acc[mf][nf];
            if (r0 < n_nodes) {
                float2 o = make_float2(fmaxf(a[0], 0.f), fmaxf(a[1], 0.f));
                *(float2*)(out + (size_t)r0 * OUT_DIM + col) = o;
            }
            if (r1 < n_nodes) {
                float2 o = make_float2(fmaxf(a[2], 0.f), fmaxf(a[3], 0.f));
                *(float2*)(out + (size_t)r1 * OUT_DIM + col) = o;
            }
        }
    }
}

// ============================== launch =====================================
extern "C" void kernel_launch(void* const* d_in, const int* in_sizes, int n_in,
                              void* d_out, int out_size) {
    const float* x    = (const float*)d_in[0];
    const int*   rows = (const int*)  d_in[1];
    const int*   cols = (const int*)  d_in[2];
    const float* vals = (const float*)d_in[3];
    const float* W    = (const float*)d_in[4];
    float*       out  = (float*)d_out;

    const int n_nodes = in_sizes[0] / D_FEAT;
    const int n_edges = in_sizes[1];
    const int nb      = (n_nodes + SCAN_BLK - 1) / SCAN_BLK;

    prep_kernel<<<(CNT_PAD + 255) / 256, 256>>>(W, n_nodes, n_edges);
    hist_kernel<<<(n_edges + 255) / 256, 256>>>(rows, n_edges);
    scan_reduce_kernel<<<nb, 256>>>(n_nodes);
    scan_write_kernel<<<nb, SCAN_BLK>>>(n_nodes, nb);
    scatter_kernel<<<(n_edges + 255) / 256, 256>>>(rows, cols, vals, n_edges);

    cudaFuncSetAttribute(fused_kernel,
                         cudaFuncAttributeMaxDynamicSharedMemorySize, SM_TOTAL);
    fused_kernel<<<(n_nodes + TM - 1) / TM, FT, SM_TOTAL>>>(x, out, n_nodes);
}

// round 7
// speedup vs baseline: 1.0541x; 1.0173x over previous
#include <cuda_runtime.h>
#include <cuda_bf16.h>
#include <cstdint>

#define D_FEAT    128
#define OUT_DIM   128
#define MAX_NODES 100000
#define MAX_EDGES 600000
#define SCAN_BLK  1024
#define CNT_PAD   102400

#define TM   128          // rows per GEMM tile
#define LDA  136          // padded bf16 row (272 B stride)
#define GT   512          // GEMM threads (16 warps)

// ---- device scratch (allocation-free) ----
__device__ float g_h[(size_t)MAX_NODES * D_FEAT];
__device__ __align__(16) int g_cnt[CNT_PAD];
__device__ int   g_off[MAX_NODES + 1];
__device__ int   g_cur[MAX_NODES];
__device__ int   g_bsum[128];
__device__ int2  g_edge[MAX_EDGES];
// bf16 hi/lo images of B chunks: [chunk][part][n=128][k padded to LDA]
__device__ uint4 g_Bimg4[2 * 4352];   // 2 x 69632 B

// ============================ PTX helpers =================================
__device__ __forceinline__ uint32_t smem_u32(const void* p) {
    uint32_t a;
    asm("{ .reg .u64 t; cvta.to.shared.u64 t, %1; cvt.u32.u64 %0, t; }" : "=r"(a) : "l"(p));
    return a;
}
__device__ __forceinline__ void ldsm4(uint32_t* r, uint32_t addr) {
    asm volatile("ldmatrix.sync.aligned.m8n8.x4.shared.b16 {%0,%1,%2,%3}, [%4];"
                 : "=r"(r[0]), "=r"(r[1]), "=r"(r[2]), "=r"(r[3]) : "r"(addr));
}
__device__ __forceinline__ void mma_bf16(float* d, const uint32_t* a,
                                         uint32_t b0, uint32_t b1) {
    asm volatile(
        "mma.sync.aligned.m16n8k16.row.col.f32.bf16.bf16.f32 "
        "{%0,%1,%2,%3}, {%4,%5,%6,%7}, {%8,%9}, {%0,%1,%2,%3};"
        : "+f"(d[0]), "+f"(d[1]), "+f"(d[2]), "+f"(d[3])
        : "r"(a[0]), "r"(a[1]), "r"(a[2]), "r"(a[3]), "r"(b0), "r"(b1));
}
__device__ __forceinline__ uint32_t bf16x2(float y, float x) {
    uint32_t r; asm("cvt.rn.bf16x2.f32 %0, %1, %2;" : "=r"(r) : "f"(y), "f"(x)); return r;
}

// ================= prep: zero counts + build B images ======================
__global__ void prep_kernel(const float* __restrict__ W, int n, int n_edges) {
    int i = blockIdx.x * blockDim.x + threadIdx.x;
    if (i < CNT_PAD) g_cnt[i] = 0;
    if (i == 0) g_off[n] = n_edges;
    if (i < 2 * 128 * 128) {
        int c = i >> 14;
        int r = i & 16383;
        int k = r >> 7;
        int nn = r & 127;
        float w = W[(size_t)(c * 128 + k) * OUT_DIM + nn];
        __nv_bfloat16 hb = __float2bfloat16(w);
        __nv_bfloat16 lb = __float2bfloat16(w - __bfloat162float(hb));
        __nv_bfloat16* img = (__nv_bfloat16*)g_Bimg4;
        img[(((size_t)c * 2 + 0) * 128 + nn) * LDA + k] = hb;
        img[(((size_t)c * 2 + 1) * 128 + nn) * LDA + k] = lb;
    }
}

// ========================= CSR build kernels ===============================
__global__ void hist_kernel(const int* __restrict__ rows, int n_edges) {
    int i = blockIdx.x * blockDim.x + threadIdx.x;
    if (i < n_edges) atomicAdd(&g_cnt[rows[i]], 1);
}

__global__ void scan_reduce_kernel(int n) {
    __shared__ int ws[8];
    int t = threadIdx.x;
    int4 v = ((const int4*)g_cnt)[blockIdx.x * 256 + t];
    int s = v.x + v.y + v.z + v.w;
#pragma unroll
    for (int o = 16; o > 0; o >>= 1) s += __shfl_xor_sync(~0u, s, o);
    if ((t & 31) == 0) ws[t >> 5] = s;
    __syncthreads();
    if (t < 8) {
        s = ws[t];
#pragma unroll
        for (int o = 4; o > 0; o >>= 1) s += __shfl_xor_sync(0xffu, s, o);
        if (t == 0) g_bsum[blockIdx.x] = s;
    }
}

__global__ void scan_write_kernel(int n, int nb) {
    __shared__ int wsum[32];
    __shared__ int sbase;
    int t = threadIdx.x, lane = t & 31, w = t >> 5;

    if (w == 0) {
        int lim = min((int)blockIdx.x, nb);
        int b = 0;
        for (int j = lane; j < lim; j += 32) b += g_bsum[j];
#pragma unroll
        for (int o = 16; o > 0; o >>= 1) b += __shfl_xor_sync(~0u, b, o);
        if (lane == 0) sbase = b;
    }

    int i = blockIdx.x * SCAN_BLK + t;
    int v = (i < n) ? g_cnt[i] : 0;
    int s = v;
#pragma unroll
    for (int d = 1; d < 32; d <<= 1) {
        int q = __shfl_up_sync(~0u, s, d);
        if (lane >= d) s += q;
    }
    if (lane == 31) wsum[w] = s;
    __syncthreads();
    if (w == 0) {
        int q = wsum[lane];
#pragma unroll
        for (int d = 1; d < 32; d <<= 1) {
            int r = __shfl_up_sync(~0u, q, d);
            if (lane >= d) q += r;
        }
        wsum[lane] = q;
    }
    __syncthreads();
    if (i < n) {
        int wbase = (w > 0) ? wsum[w - 1] : 0;
        int o = sbase + wbase + s - v;
        g_off[i] = o;
        g_cur[i] = o;
    }
}

__global__ void scatter_kernel(const int* __restrict__ rows,
                               const int* __restrict__ cols,
                               const float* __restrict__ vals,
                               int n_edges) {
    int i = blockIdx.x * blockDim.x + threadIdx.x;
    if (i < n_edges) {
        int r = rows[i];
        int p = atomicAdd(&g_cur[r], 1);
        g_edge[p] = make_int2(cols[i], __float_as_int(vals[i]));
    }
}

// ============ SpMM: warp per row, full occupancy, x4 unrolled ==============
__global__ void spmm_csr_kernel(const float* __restrict__ x, int n_nodes) {
    int row  = (blockIdx.x * blockDim.x + threadIdx.x) >> 5;
    int lane = threadIdx.x & 31;
    if (row >= n_nodes) return;

    int e  = g_off[row];
    int e1 = g_off[row + 1];

    float4 aA = make_float4(0.f, 0.f, 0.f, 0.f);
    float4 aB = make_float4(0.f, 0.f, 0.f, 0.f);
    for (; e + 4 <= e1; e += 4) {
        int2 e0 = g_edge[e],     e1v = g_edge[e + 1];
        int2 e2 = g_edge[e + 2], e3v = g_edge[e + 3];
        float4 x0 = ((const float4*)(x + (size_t)e0.x  * D_FEAT))[lane];
        float4 x1 = ((const float4*)(x + (size_t)e1v.x * D_FEAT))[lane];
        float4 x2 = ((const float4*)(x + (size_t)e2.x  * D_FEAT))[lane];
        float4 x3 = ((const float4*)(x + (size_t)e3v.x * D_FEAT))[lane];
        float v0 = __int_as_float(e0.y),  v1 = __int_as_float(e1v.y);
        float v2 = __int_as_float(e2.y),  v3 = __int_as_float(e3v.y);
        aA.x = fmaf(v0, x0.x, aA.x); aA.y = fmaf(v0, x0.y, aA.y);
        aA.z = fmaf(v0, x0.z, aA.z); aA.w = fmaf(v0, x0.w, aA.w);
        aB.x = fmaf(v1, x1.x, aB.x); aB.y = fmaf(v1, x1.y, aB.y);
        aB.z = fmaf(v1, x1.z, aB.z); aB.w = fmaf(v1, x1.w, aB.w);
        aA.x = fmaf(v2, x2.x, aA.x); aA.y = fmaf(v2, x2.y, aA.y);
        aA.z = fmaf(v2, x2.z, aA.z); aA.w = fmaf(v2, x2.w, aA.w);
        aB.x = fmaf(v3, x3.x, aB.x); aB.y = fmaf(v3, x3.y, aB.y);
        aB.z = fmaf(v3, x3.z, aB.z); aB.w = fmaf(v3, x3.w, aB.w);
    }
    for (; e < e1; e++) {
        int2 ev = g_edge[e];
        float4 xv = ((const float4*)(x + (size_t)ev.x * D_FEAT))[lane];
        float v = __int_as_float(ev.y);
        aA.x = fmaf(v, xv.x, aA.x); aA.y = fmaf(v, xv.y, aA.y);
        aA.z = fmaf(v, xv.z, aA.z); aA.w = fmaf(v, xv.w, aA.w);
    }
    float4 acc = make_float4(aA.x + aB.x, aA.y + aB.y, aA.z + aB.z, aA.w + aB.w);
    ((float4*)(g_h + (size_t)row * D_FEAT))[lane] = acc;
}

// ========== GEMM: out = relu([h|x] @ W), 16 warps, B fully resident ========
// smem: A hi (34816) | A lo (34816) | Bc0 hi (34816) | Bc0 lo | Bc1 hi | Bc1 lo
#define SM_A     0
#define SM_PART  34816
#define SM_B     69632
#define SM_TOTAL 208896

__global__ __launch_bounds__(GT, 1)
void gemm_mma_kernel(const float* __restrict__ x,
                     float* __restrict__ out,
                     int n_nodes) {
    extern __shared__ char smem[];
    const uint32_t sbase = smem_u32(smem);
    const int tid  = threadIdx.x;
    const int wid  = tid >> 5;
    const int lane = tid & 31;
    const int wm   = wid >> 2;      // 0..3  : 32-row strip
    const int wn   = wid & 3;       // 0..3  : 32-col strip
    const int row0 = blockIdx.x * TM;

    uint32_t pA[2], pBo[2];
#pragma unroll
    for (int mf = 0; mf < 2; mf++)
        pA[mf] = sbase + SM_A
               + (uint32_t)((wm * 32 + mf * 16 + (lane & 15)) * (LDA * 2))
               + (uint32_t)((lane >> 4) << 4);
#pragma unroll
    for (int p = 0; p < 2; p++)
        pBo[p] = (uint32_t)((wn * 32 + p * 16 + (lane & 7) + ((lane >> 4) << 3)) * (LDA * 2))
               + (uint32_t)((lane & 8) << 1);

    // ---- copy both B chunk images once (8704 uint4) ----
    {
        uint4* dB = (uint4*)(smem + SM_B);
#pragma unroll
        for (int j = tid; j < 8704; j += GT) dB[j] = g_Bimg4[j];
    }

    float acc[2][4][4];
#pragma unroll
    for (int mf = 0; mf < 2; mf++)
#pragma unroll
        for (int nf = 0; nf < 4; nf++)
#pragma unroll
            for (int q = 0; q < 4; q++) acc[mf][nf][q] = 0.f;

    for (int c = 0; c < 2; c++) {
        // ---- stage A chunk (h for c=0, x for c=1), split fp32 -> bf16 hi/lo
        const float* src = (c == 0) ? g_h : x;
        if (c == 1) __syncthreads();   // MMA chunk 0 done reading A
#pragma unroll
        for (int j = 0; j < (TM * 128 / 4) / GT; j++) {   // 8 iters
            int i  = tid + j * GT;
            int r  = i >> 5;
            int kq = i & 31;
            int gr = row0 + r;
            float4 v = make_float4(0.f, 0.f, 0.f, 0.f);
            if (gr < n_nodes) v = ((const float4*)(src + (size_t)gr * D_FEAT))[kq];
            uint32_t h01 = bf16x2(v.y, v.x);
            uint32_t h23 = bf16x2(v.w, v.z);
            float fx = __uint_as_float(h01 << 16);
            float fy = __uint_as_float(h01 & 0xffff0000u);
            float fz = __uint_as_float(h23 << 16);
            float fw = __uint_as_float(h23 & 0xffff0000u);
            uint32_t l01 = bf16x2(v.y - fy, v.x - fx);
            uint32_t l23 = bf16x2(v.w - fw, v.z - fz);
            char* dst = smem + SM_A + r * (LDA * 2) + kq * 8;
            *(uint2*)dst             = make_uint2(h01, h23);
            *(uint2*)(dst + SM_PART) = make_uint2(l01, l23);
        }
        __syncthreads();

        const uint32_t bbase = sbase + SM_B + (uint32_t)c * 69632u;
#pragma unroll
        for (int ks = 0; ks < 8; ks++) {
            const uint32_t k0b = (uint32_t)(ks << 5);
            uint32_t Ah[2][4], Al[2][4];
#pragma unroll
            for (int mf = 0; mf < 2; mf++) {
                ldsm4(Ah[mf], pA[mf] + k0b);
                ldsm4(Al[mf], pA[mf] + SM_PART + k0b);
            }
#pragma unroll
            for (int p = 0; p < 2; p++) {
                uint32_t Bh[4], Bl[4];
                ldsm4(Bh, bbase + pBo[p] + k0b);
                ldsm4(Bl, bbase + pBo[p] + SM_PART + k0b);
#pragma unroll
                for (int mf = 0; mf < 2; mf++) {
                    float* a0 = acc[mf][2 * p];
                    float* a1 = acc[mf][2 * p + 1];
                    mma_bf16(a0, Ah[mf], Bh[0], Bh[1]);
                    mma_bf16(a1, Ah[mf], Bh[2], Bh[3]);
                    mma_bf16(a0, Al[mf], Bh[0], Bh[1]);
                    mma_bf16(a1, Al[mf], Bh[2], Bh[3]);
                    mma_bf16(a0, Ah[mf], Bl[0], Bl[1]);
                    mma_bf16(a1, Ah[mf], Bl[2], Bl[3]);
                }
            }
        }
    }

    // ---- epilogue: relu + store ----
#pragma unroll
    for (int mf = 0; mf < 2; mf++) {
        int r0 = row0 + wm * 32 + mf * 16 + (lane >> 2);
        int r1 = r0 + 8;
#pragma unroll
        for (int nf = 0; nf < 4; nf++) {
            int col = wn * 32 + nf * 8 + (lane & 3) * 2;
            float* a = acc[mf][nf];
            if (r0 < n_nodes) {
                float2 o = make_float2(fmaxf(a[0], 0.f), fmaxf(a[1], 0.f));
                *(float2*)(out + (size_t)r0 * OUT_DIM + col) = o;
            }
            if (r1 < n_nodes) {
                float2 o = make_float2(fmaxf(a[2], 0.f), fmaxf(a[3], 0.f));
                *(float2*)(out + (size_t)r1 * OUT_DIM + col) = o;
            }
        }
    }
}

// ============================== launch =====================================
extern "C" void kernel_launch(void* const* d_in, const int* in_sizes, int n_in,
                              void* d_out, int out_size) {
    const float* x    = (const float*)d_in[0];
    const int*   rows = (const int*)  d_in[1];
    const int*   cols = (const int*)  d_in[2];
    const float* vals = (const float*)d_in[3];
    const float* W    = (const float*)d_in[4];
    float*       out  = (float*)d_out;

    const int n_nodes = in_sizes[0] / D_FEAT;
    const int n_edges = in_sizes[1];
    const int nb      = (n_nodes + SCAN_BLK - 1) / SCAN_BLK;

    prep_kernel<<<(CNT_PAD + 255) / 256, 256>>>(W, n_nodes, n_edges);
    hist_kernel<<<(n_edges + 255) / 256, 256>>>(rows, n_edges);
    scan_reduce_kernel<<<nb, 256>>>(n_nodes);
    scan_write_kernel<<<nb, SCAN_BLK>>>(n_nodes, nb);
    scatter_kernel<<<(n_edges + 255) / 256, 256>>>(rows, cols, vals, n_edges);

    long long spmm_threads = (long long)n_nodes * 32;
    spmm_csr_kernel<<<(int)((spmm_threads + 255) / 256), 256>>>(x, n_nodes);

    cudaFuncSetAttribute(gemm_mma_kernel,
                         cudaFuncAttributeMaxDynamicSharedMemorySize, SM_TOTAL);
    gemm_mma_kernel<<<(n_nodes + TM - 1) / TM, GT, SM_TOTAL>>>(x, out, n_nodes);
}

// round 8
// speedup vs baseline: 1.1213x; 1.0638x over previous
#include <cuda_runtime.h>
#include <cuda_bf16.h>
#include <cstdint>

#define D_FEAT    128
#define OUT_DIM   128
#define MAX_NODES 100000
#define MAX_EDGES 600000
#define SCAN_BLK  1024
#define CNT_PAD   102400

#define TM   128          // rows per GEMM tile
#define CK   128          // K per chunk (2 chunks: h then x)
#define LDA  136          // padded bf16 row (272 B stride)
#define GT   256          // GEMM threads (8 warps) — R4 proven config

// ---- device scratch (allocation-free) ----
__device__ float g_h[(size_t)MAX_NODES * D_FEAT];
__device__ __align__(16) int g_cnt[CNT_PAD];
__device__ int   g_off[MAX_NODES + 1];
__device__ int   g_cur[MAX_NODES];
__device__ int   g_bsum[128];
__device__ int2  g_edge[MAX_EDGES];
// bf16 hi/lo images of B chunks: [chunk][part][n=128][k padded to LDA]
__device__ uint4 g_Bimg4[2 * 4352];   // 2 x 69632 B

// ============================ PTX helpers =================================
__device__ __forceinline__ uint32_t smem_u32(const void* p) {
    uint32_t a;
    asm("{ .reg .u64 t; cvta.to.shared.u64 t, %1; cvt.u32.u64 %0, t; }" : "=r"(a) : "l"(p));
    return a;
}
__device__ __forceinline__ void ldsm4(uint32_t* r, uint32_t addr) {
    asm volatile("ldmatrix.sync.aligned.m8n8.x4.shared.b16 {%0,%1,%2,%3}, [%4];"
                 : "=r"(r[0]), "=r"(r[1]), "=r"(r[2]), "=r"(r[3]) : "r"(addr));
}
__device__ __forceinline__ void mma_bf16(float* d, const uint32_t* a,
                                         uint32_t b0, uint32_t b1) {
    asm volatile(
        "mma.sync.aligned.m16n8k16.row.col.f32.bf16.bf16.f32 "
        "{%0,%1,%2,%3}, {%4,%5,%6,%7}, {%8,%9}, {%0,%1,%2,%3};"
        : "+f"(d[0]), "+f"(d[1]), "+f"(d[2]), "+f"(d[3])
        : "r"(a[0]), "r"(a[1]), "r"(a[2]), "r"(a[3]), "r"(b0), "r"(b1));
}
__device__ __forceinline__ uint32_t bf16x2(float y, float x) {
    uint32_t r; asm("cvt.rn.bf16x2.f32 %0, %1, %2;" : "=r"(r) : "f"(y), "f"(x)); return r;
}

// ================= prep: zero counts + build B images ======================
__global__ void prep_kernel(const float* __restrict__ W, int n, int n_edges) {
    int i = blockIdx.x * blockDim.x + threadIdx.x;
    if (i < CNT_PAD) g_cnt[i] = 0;
    if (i == 0) g_off[n] = n_edges;
    if (i < 2 * 128 * 128) {
        int c = i >> 14;
        int r = i & 16383;
        int k = r >> 7;
        int nn = r & 127;
        float w = W[(size_t)(c * 128 + k) * OUT_DIM + nn];
        __nv_bfloat16 hb = __float2bfloat16(w);
        __nv_bfloat16 lb = __float2bfloat16(w - __bfloat162float(hb));
        __nv_bfloat16* img = (__nv_bfloat16*)g_Bimg4;
        img[(((size_t)c * 2 + 0) * 128 + nn) * LDA + k] = hb;
        img[(((size_t)c * 2 + 1) * 128 + nn) * LDA + k] = lb;
    }
}

// ========================= CSR build kernels ===============================
__global__ void hist_kernel(const int* __restrict__ rows, int n_edges) {
    int i = blockIdx.x * blockDim.x + threadIdx.x;
    if (i < n_edges) atomicAdd(&g_cnt[rows[i]], 1);
}

__global__ void scan_reduce_kernel(int n) {
    __shared__ int ws[8];
    int t = threadIdx.x;
    int4 v = ((const int4*)g_cnt)[blockIdx.x * 256 + t];
    int s = v.x + v.y + v.z + v.w;
#pragma unroll
    for (int o = 16; o > 0; o >>= 1) s += __shfl_xor_sync(~0u, s, o);
    if ((t & 31) == 0) ws[t >> 5] = s;
    __syncthreads();
    if (t < 8) {
        s = ws[t];
#pragma unroll
        for (int o = 4; o > 0; o >>= 1) s += __shfl_xor_sync(0xffu, s, o);
        if (t == 0) g_bsum[blockIdx.x] = s;
    }
}

__global__ void scan_write_kernel(int n, int nb) {
    __shared__ int wsum[32];
    __shared__ int sbase;
    int t = threadIdx.x, lane = t & 31, w = t >> 5;

    if (w == 0) {
        int lim = min((int)blockIdx.x, nb);
        int b = 0;
        for (int j = lane; j < lim; j += 32) b += g_bsum[j];
#pragma unroll
        for (int o = 16; o > 0; o >>= 1) b += __shfl_xor_sync(~0u, b, o);
        if (lane == 0) sbase = b;
    }

    int i = blockIdx.x * SCAN_BLK + t;
    int v = (i < n) ? g_cnt[i] : 0;
    int s = v;
#pragma unroll
    for (int d = 1; d < 32; d <<= 1) {
        int q = __shfl_up_sync(~0u, s, d);
        if (lane >= d) s += q;
    }
    if (lane == 31) wsum[w] = s;
    __syncthreads();
    if (w == 0) {
        int q = wsum[lane];
#pragma unroll
        for (int d = 1; d < 32; d <<= 1) {
            int r = __shfl_up_sync(~0u, q, d);
            if (lane >= d) q += r;
        }
        wsum[lane] = q;
    }
    __syncthreads();
    if (i < n) {
        int wbase = (w > 0) ? wsum[w - 1] : 0;
        int o = sbase + wbase + s - v;
        g_off[i] = o;
        g_cur[i] = o;
    }
}

__global__ void scatter_kernel(const int* __restrict__ rows,
                               const int* __restrict__ cols,
                               const float* __restrict__ vals,
                               int n_edges) {
    int i = blockIdx.x * blockDim.x + threadIdx.x;
    if (i < n_edges) {
        int r = rows[i];
        int p = atomicAdd(&g_cur[r], 1);
        g_edge[p] = make_int2(cols[i], __float_as_int(vals[i]));
    }
}

// ============ SpMM: warp per row, full occupancy, x4 unrolled ==============
__global__ void spmm_csr_kernel(const float* __restrict__ x, int n_nodes) {
    int row  = (blockIdx.x * blockDim.x + threadIdx.x) >> 5;
    int lane = threadIdx.x & 31;
    if (row >= n_nodes) return;

    int e  = g_off[row];
    int e1 = g_off[row + 1];

    float4 aA = make_float4(0.f, 0.f, 0.f, 0.f);
    float4 aB = make_float4(0.f, 0.f, 0.f, 0.f);
    for (; e + 4 <= e1; e += 4) {
        int2 e0 = g_edge[e],     e1v = g_edge[e + 1];
        int2 e2 = g_edge[e + 2], e3v = g_edge[e + 3];
        float4 x0 = ((const float4*)(x + (size_t)e0.x  * D_FEAT))[lane];
        float4 x1 = ((const float4*)(x + (size_t)e1v.x * D_FEAT))[lane];
        float4 x2 = ((const float4*)(x + (size_t)e2.x  * D_FEAT))[lane];
        float4 x3 = ((const float4*)(x + (size_t)e3v.x * D_FEAT))[lane];
        float v0 = __int_as_float(e0.y),  v1 = __int_as_float(e1v.y);
        float v2 = __int_as_float(e2.y),  v3 = __int_as_float(e3v.y);
        aA.x = fmaf(v0, x0.x, aA.x); aA.y = fmaf(v0, x0.y, aA.y);
        aA.z = fmaf(v0, x0.z, aA.z); aA.w = fmaf(v0, x0.w, aA.w);
        aB.x = fmaf(v1, x1.x, aB.x); aB.y = fmaf(v1, x1.y, aB.y);
        aB.z = fmaf(v1, x1.z, aB.z); aB.w = fmaf(v1, x1.w, aB.w);
        aA.x = fmaf(v2, x2.x, aA.x); aA.y = fmaf(v2, x2.y, aA.y);
        aA.z = fmaf(v2, x2.z, aA.z); aA.w = fmaf(v2, x2.w, aA.w);
        aB.x = fmaf(v3, x3.x, aB.x); aB.y = fmaf(v3, x3.y, aB.y);
        aB.z = fmaf(v3, x3.z, aB.z); aB.w = fmaf(v3, x3.w, aB.w);
    }
    for (; e < e1; e++) {
        int2 ev = g_edge[e];
        float4 xv = ((const float4*)(x + (size_t)ev.x * D_FEAT))[lane];
        float v = __int_as_float(ev.y);
        aA.x = fmaf(v, xv.x, aA.x); aA.y = fmaf(v, xv.y, aA.y);
        aA.z = fmaf(v, xv.z, aA.z); aA.w = fmaf(v, xv.w, aA.w);
    }
    float4 acc = make_float4(aA.x + aB.x, aA.y + aB.y, aA.z + aB.z, aA.w + aB.w);
    ((float4*)(g_h + (size_t)row * D_FEAT))[lane] = acc;
}

// ====== GEMM (R4-proven): out = relu([h|x] @ W), 8 warps, per-chunk B ======
// smem: A hi [128][LDA] (34816 B) | A lo (34816) | B hi (34816) | B lo (34816)
#define SM_A     0
#define SM_PART  34816
#define SM_B     69632
#define SM_TOTAL 139264

__global__ __launch_bounds__(GT, 1)
void gemm_mma_kernel(const float* __restrict__ x,
                     float* __restrict__ out,
                     int n_nodes) {
    extern __shared__ char smem[];
    const uint32_t sbase = smem_u32(smem);
    const int tid  = threadIdx.x;
    const int wid  = tid >> 5;
    const int lane = tid & 31;
    const int wm   = wid >> 1;       // 0..3  (32-row strip)
    const int wn   = wid & 1;        // 0..1  (64-col strip)
    const int row0 = blockIdx.x * TM;

    uint32_t pA[2], pB[4];
#pragma unroll
    for (int mf = 0; mf < 2; mf++)
        pA[mf] = sbase + SM_A
               + (uint32_t)((wm * 32 + mf * 16 + (lane & 15)) * (LDA * 2))
               + (uint32_t)((lane >> 4) << 4);
#pragma unroll
    for (int p = 0; p < 4; p++)
        pB[p] = sbase + SM_B
              + (uint32_t)((wn * 64 + p * 16 + (lane & 7) + ((lane >> 4) << 3)) * (LDA * 2))
              + (uint32_t)((lane & 8) << 1);

    float acc[2][8][4];
#pragma unroll
    for (int mf = 0; mf < 2; mf++)
#pragma unroll
        for (int nf = 0; nf < 8; nf++)
#pragma unroll
            for (int q = 0; q < 4; q++) acc[mf][nf][q] = 0.f;

    for (int c = 0; c < 2; c++) {
        // ---- stage A chunk (h for c=0, x for c=1), split fp32 -> bf16 hi/lo
        const float* src = (c == 0) ? g_h : x;
#pragma unroll
        for (int j = 0; j < (TM * CK / 4) / GT; j++) {       // 16 iters
            int i  = tid + j * GT;
            int r  = i >> 5;
            int kq = i & 31;
            int gr = row0 + r;
            float4 v = make_float4(0.f, 0.f, 0.f, 0.f);
            if (gr < n_nodes) v = ((const float4*)(src + (size_t)gr * D_FEAT))[kq];
            uint32_t h01 = bf16x2(v.y, v.x);
            uint32_t h23 = bf16x2(v.w, v.z);
            float fx = __uint_as_float(h01 << 16);
            float fy = __uint_as_float(h01 & 0xffff0000u);
            float fz = __uint_as_float(h23 << 16);
            float fw = __uint_as_float(h23 & 0xffff0000u);
            uint32_t l01 = bf16x2(v.y - fy, v.x - fx);
            uint32_t l23 = bf16x2(v.w - fw, v.z - fz);
            char* dst = smem + SM_A + r * (LDA * 2) + kq * 8;
            *(uint2*)dst             = make_uint2(h01, h23);
            *(uint2*)(dst + SM_PART) = make_uint2(l01, l23);
        }
        // ---- copy prebuilt B chunk image (hi+lo contiguous) ----
        {
            const uint4* sB = g_Bimg4 + (size_t)c * 4352;
            uint4* dB = (uint4*)(smem + SM_B);
#pragma unroll
            for (int j = tid; j < 4352; j += GT) dB[j] = sB[j];
        }
        __syncthreads();

        // ---- MMA mainloop: 8 k-steps of 16 ----
#pragma unroll
        for (int ks = 0; ks < CK / 16; ks++) {
            const uint32_t k0b = (uint32_t)(ks << 5);
            uint32_t Ah[2][4], Al[2][4];
#pragma unroll
            for (int mf = 0; mf < 2; mf++) {
                ldsm4(Ah[mf], pA[mf] + k0b);
                ldsm4(Al[mf], pA[mf] + SM_PART + k0b);
            }
            uint32_t Bh[4][4], Bl[4][4];
#pragma unroll
            for (int p = 0; p < 4; p++) {
                ldsm4(Bh[p], pB[p] + k0b);
                ldsm4(Bl[p], pB[p] + SM_PART + k0b);
            }
#pragma unroll
            for (int mf = 0; mf < 2; mf++)
#pragma unroll
                for (int p = 0; p < 4; p++) {
                    mma_bf16(acc[mf][2 * p],     Ah[mf], Bh[p][0], Bh[p][1]);
                    mma_bf16(acc[mf][2 * p + 1], Ah[mf], Bh[p][2], Bh[p][3]);
                    mma_bf16(acc[mf][2 * p],     Al[mf], Bh[p][0], Bh[p][1]);
                    mma_bf16(acc[mf][2 * p + 1], Al[mf], Bh[p][2], Bh[p][3]);
                    mma_bf16(acc[mf][2 * p],     Ah[mf], Bl[p][0], Bl[p][1]);
                    mma_bf16(acc[mf][2 * p + 1], Ah[mf], Bl[p][2], Bl[p][3]);
                }
        }
        __syncthreads();   // before restaging smem for next chunk
    }

    // ---- epilogue: relu + store ----
#pragma unroll
    for (int mf = 0; mf < 2; mf++) {
        int gr0 = row0 + wm * 32 + mf * 16 + (lane >> 2);
#pragma unroll
        for (int nf = 0; nf < 8; nf++) {
            int col = wn * 64 + (nf >> 1) * 16 + (nf & 1) * 8 + (lane & 3) * 2;
            float* a = acc[mf][nf];
            if (gr0 < n_nodes) {
                float2 o0 = make_float2(fmaxf(a[0], 0.f), fmaxf(a[1], 0.f));
                *(float2*)(out + (size_t)gr0 * OUT_DIM + col) = o0;
            }
            if (gr0 + 8 < n_nodes) {
                float2 o1 = make_float2(fmaxf(a[2], 0.f), fmaxf(a[3], 0.f));
                *(float2*)(out + (size_t)(gr0 + 8) * OUT_DIM + col) = o1;
            }
        }
    }
}

// ============================== launch =====================================
extern "C" void kernel_launch(void* const* d_in, const int* in_sizes, int n_in,
                              void* d_out, int out_size) {
    const float* x    = (const float*)d_in[0];
    const int*   rows = (const int*)  d_in[1];
    const int*   cols = (const int*)  d_in[2];
    const float* vals = (const float*)d_in[3];
    const float* W    = (const float*)d_in[4];
    float*       out  = (float*)d_out;

    const int n_nodes = in_sizes[0] / D_FEAT;
    const int n_edges = in_sizes[1];
    const int nb      = (n_nodes + SCAN_BLK - 1) / SCAN_BLK;

    prep_kernel<<<(CNT_PAD + 255) / 256, 256>>>(W, n_nodes, n_edges);
    hist_kernel<<<(n_edges + 255) / 256, 256>>>(rows, n_edges);
    scan_reduce_kernel<<<nb, 256>>>(n_nodes);
    scan_write_kernel<<<nb, SCAN_BLK>>>(n_nodes, nb);
    scatter_kernel<<<(n_edges + 255) / 256, 256>>>(rows, cols, vals, n_edges);

    long long spmm_threads = (long long)n_nodes * 32;
    spmm_csr_kernel<<<(int)((spmm_threads + 255) / 256), 256>>>(x, n_nodes);

    cudaFuncSetAttribute(gemm_mma_kernel,
                         cudaFuncAttributeMaxDynamicSharedMemorySize, SM_TOTAL);
    gemm_mma_kernel<<<(n_nodes + TM - 1) / TM, GT, SM_TOTAL>>>(x, out, n_nodes);
}

// round 9
// speedup vs baseline: 1.1424x; 1.0188x over previous
#include <cuda_runtime.h>
#include <cuda_bf16.h>
#include <cstdint>

#define D_FEAT    128
#define OUT_DIM   128
#define MAX_NODES 100000
#define MAX_EDGES 600000
#define SCAN_BLK  1024
#define CNT_PAD   102400

#define TM   128          // rows per GEMM tile
#define CK   128          // K per chunk (2 chunks: h then x)
#define LDA  136          // padded bf16 row (272 B stride)
#define GT   256          // GEMM threads (8 warps)

// ---- device scratch (allocation-free) ----
__device__ float g_h[(size_t)MAX_NODES * D_FEAT];
__device__ __align__(16) int g_cnt[CNT_PAD];   // zero-init; self-cleaned by scan_write
__device__ int   g_off[MAX_NODES + 1];
__device__ int   g_cur[MAX_NODES];
__device__ int   g_bsum[128];
__device__ int2  g_edge[MAX_EDGES];
// bf16 hi/lo images of B chunks: [chunk][part][n=128][k padded to LDA]
__device__ uint4 g_Bimg4[2 * 4352];   // 2 x 69632 B

// ============================ PTX helpers =================================
__device__ __forceinline__ uint32_t smem_u32(const void* p) {
    uint32_t a;
    asm("{ .reg .u64 t; cvta.to.shared.u64 t, %1; cvt.u32.u64 %0, t; }" : "=r"(a) : "l"(p));
    return a;
}
__device__ __forceinline__ void ldsm4(uint32_t* r, uint32_t addr) {
    asm volatile("ldmatrix.sync.aligned.m8n8.x4.shared.b16 {%0,%1,%2,%3}, [%4];"
                 : "=r"(r[0]), "=r"(r[1]), "=r"(r[2]), "=r"(r[3]) : "r"(addr));
}
__device__ __forceinline__ void mma_bf16(float* d, const uint32_t* a,
                                         uint32_t b0, uint32_t b1) {
    asm volatile(
        "mma.sync.aligned.m16n8k16.row.col.f32.bf16.bf16.f32 "
        "{%0,%1,%2,%3}, {%4,%5,%6,%7}, {%8,%9}, {%0,%1,%2,%3};"
        : "+f"(d[0]), "+f"(d[1]), "+f"(d[2]), "+f"(d[3])
        : "r"(a[0]), "r"(a[1]), "r"(a[2]), "r"(a[3]), "r"(b0), "r"(b1));
}
__device__ __forceinline__ uint32_t bf16x2(float y, float x) {
    uint32_t r; asm("cvt.rn.bf16x2.f32 %0, %1, %2;" : "=r"(r) : "f"(y), "f"(x)); return r;
}
__device__ __forceinline__ void cpa16(uint32_t dst, const void* src) {
    asm volatile("cp.async.cg.shared.global [%0], [%1], 16;" :: "r"(dst), "l"(src));
}
__device__ __forceinline__ void cpa16z(uint32_t dst, const void* src, int valid) {
    int sz = valid ? 16 : 0;
    asm volatile("cp.async.cg.shared.global [%0], [%1], 16, %2;"
                 :: "r"(dst), "l"(src), "r"(sz));
}
__device__ __forceinline__ void cpa_commit() {
    asm volatile("cp.async.commit_group;" ::: "memory");
}
template <int N>
__device__ __forceinline__ void cpa_wait() {
    asm volatile("cp.async.wait_group %0;" :: "n"(N) : "memory");
}

// ============ hist + prep fused: edge histogram + B image build ============
__global__ void hist_prep_kernel(const int* __restrict__ rows,
                                 const float* __restrict__ W,
                                 int n, int n_edges) {
    int i = blockIdx.x * blockDim.x + threadIdx.x;
    if (i < 2 * 128 * 128) {
        int c = i >> 14;
        int r = i & 16383;
        int k = r >> 7;
        int nn = r & 127;
        float w = W[(size_t)(c * 128 + k) * OUT_DIM + nn];
        __nv_bfloat16 hb = __float2bfloat16(w);
        __nv_bfloat16 lb = __float2bfloat16(w - __bfloat162float(hb));
        __nv_bfloat16* img = (__nv_bfloat16*)g_Bimg4;
        img[(((size_t)c * 2 + 0) * 128 + nn) * LDA + k] = hb;
        img[(((size_t)c * 2 + 1) * 128 + nn) * LDA + k] = lb;
    }
    if (i < n_edges) atomicAdd(&g_cnt[rows[i]], 1);
}

// ========================= scan kernels ====================================
__global__ void scan_reduce_kernel(int n) {
    __shared__ int ws[8];
    int t = threadIdx.x;
    int4 v = ((const int4*)g_cnt)[blockIdx.x * 256 + t];   // pad region stays 0
    int s = v.x + v.y + v.z + v.w;
#pragma unroll
    for (int o = 16; o > 0; o >>= 1) s += __shfl_xor_sync(~0u, s, o);
    if ((t & 31) == 0) ws[t >> 5] = s;
    __syncthreads();
    if (t < 8) {
        s = ws[t];
#pragma unroll
        for (int o = 4; o > 0; o >>= 1) s += __shfl_xor_sync(0xffu, s, o);
        if (t == 0) g_bsum[blockIdx.x] = s;
    }
}

// fused block-base + shuffle exclusive scan; self-cleans g_cnt; sets g_off[n]
__global__ void scan_write_kernel(int n, int nb, int n_edges) {
    __shared__ int wsum[32];
    __shared__ int sbase;
    int t = threadIdx.x, lane = t & 31, w = t >> 5;

    if (w == 0) {
        int lim = min((int)blockIdx.x, nb);
        int b = 0;
        for (int j = lane; j < lim; j += 32) b += g_bsum[j];
#pragma unroll
        for (int o = 16; o > 0; o >>= 1) b += __shfl_xor_sync(~0u, b, o);
        if (lane == 0) sbase = b;
    }

    int i = blockIdx.x * SCAN_BLK + t;
    int v = (i < n) ? g_cnt[i] : 0;
    int s = v;
#pragma unroll
    for (int d = 1; d < 32; d <<= 1) {
        int q = __shfl_up_sync(~0u, s, d);
        if (lane >= d) s += q;
    }
    if (lane == 31) wsum[w] = s;
    __syncthreads();
    if (w == 0) {
        int q = wsum[lane];
#pragma unroll
        for (int d = 1; d < 32; d <<= 1) {
            int r = __shfl_up_sync(~0u, q, d);
            if (lane >= d) q += r;
        }
        wsum[lane] = q;
    }
    __syncthreads();
    if (i < n) {
        int wbase = (w > 0) ? wsum[w - 1] : 0;
        int o = sbase + wbase + s - v;
        g_off[i] = o;
        g_cur[i] = o;
        g_cnt[i] = 0;          // self-clean for next launch
    }
    if (i == n) g_off[n] = n_edges;
}

__global__ void scatter_kernel(const int* __restrict__ rows,
                               const int* __restrict__ cols,
                               const float* __restrict__ vals,
                               int n_edges) {
    int i = blockIdx.x * blockDim.x + threadIdx.x;
    if (i < n_edges) {
        int r = rows[i];
        int p = atomicAdd(&g_cur[r], 1);
        g_edge[p] = make_int2(cols[i], __float_as_int(vals[i]));
    }
}

// ============ SpMM: warp per row, full occupancy, x4 unrolled ==============
__global__ void spmm_csr_kernel(const float* __restrict__ x, int n_nodes) {
    int row  = (blockIdx.x * blockDim.x + threadIdx.x) >> 5;
    int lane = threadIdx.x & 31;
    if (row >= n_nodes) return;

    int e  = g_off[row];
    int e1 = g_off[row + 1];

    float4 aA = make_float4(0.f, 0.f, 0.f, 0.f);
    float4 aB = make_float4(0.f, 0.f, 0.f, 0.f);
    for (; e + 4 <= e1; e += 4) {
        int2 e0 = g_edge[e],     e1v = g_edge[e + 1];
        int2 e2 = g_edge[e + 2], e3v = g_edge[e + 3];
        float4 x0 = ((const float4*)(x + (size_t)e0.x  * D_FEAT))[lane];
        float4 x1 = ((const float4*)(x + (size_t)e1v.x * D_FEAT))[lane];
        float4 x2 = ((const float4*)(x + (size_t)e2.x  * D_FEAT))[lane];
        float4 x3 = ((const float4*)(x + (size_t)e3v.x * D_FEAT))[lane];
        float v0 = __int_as_float(e0.y),  v1 = __int_as_float(e1v.y);
        float v2 = __int_as_float(e2.y),  v3 = __int_as_float(e3v.y);
        aA.x = fmaf(v0, x0.x, aA.x); aA.y = fmaf(v0, x0.y, aA.y);
        aA.z = fmaf(v0, x0.z, aA.z); aA.w = fmaf(v0, x0.w, aA.w);
        aB.x = fmaf(v1, x1.x, aB.x); aB.y = fmaf(v1, x1.y, aB.y);
        aB.z = fmaf(v1, x1.z, aB.z); aB.w = fmaf(v1, x1.w, aB.w);
        aA.x = fmaf(v2, x2.x, aA.x); aA.y = fmaf(v2, x2.y, aA.y);
        aA.z = fmaf(v2, x2.z, aA.z); aA.w = fmaf(v2, x2.w, aA.w);
        aB.x = fmaf(v3, x3.x, aB.x); aB.y = fmaf(v3, x3.y, aB.y);
        aB.z = fmaf(v3, x3.z, aB.z); aB.w = fmaf(v3, x3.w, aB.w);
    }
    for (; e < e1; e++) {
        int2 ev = g_edge[e];
        float4 xv = ((const float4*)(x + (size_t)ev.x * D_FEAT))[lane];
        float v = __int_as_float(ev.y);
        aA.x = fmaf(v, xv.x, aA.x); aA.y = fmaf(v, xv.y, aA.y);
        aA.z = fmaf(v, xv.z, aA.z); aA.w = fmaf(v, xv.w, aA.w);
    }
    float4 acc = make_float4(aA.x + aB.x, aA.y + aB.y, aA.z + aB.z, aA.w + aB.w);
    ((float4*)(g_h + (size_t)row * D_FEAT))[lane] = acc;
}

// ====== GEMM: out = relu([h|x] @ W), cp.async pipelined, 8 warps ==========
// smem: A hi (34816) | A lo (34816) | B hi+lo (69632) | x fp32 scratch (65536)
#define SM_A     0
#define SM_PART  34816
#define SM_B     69632
#define SM_X     139264
#define SM_TOTAL 204800

__global__ __launch_bounds__(GT, 1)
void gemm_mma_kernel(const float* __restrict__ x,
                     float* __restrict__ out,
                     int n_nodes) {
    extern __shared__ char smem[];
    const uint32_t sbase = smem_u32(smem);
    const int tid  = threadIdx.x;
    const int wid  = tid >> 5;
    const int lane = tid & 31;
    const int wm   = wid >> 1;       // 0..3  (32-row strip)
    const int wn   = wid & 1;        // 0..1  (64-col strip)
    const int row0 = blockIdx.x * TM;

    uint32_t pA[2], pB[4];
#pragma unroll
    for (int mf = 0; mf < 2; mf++)
        pA[mf] = sbase + SM_A
               + (uint32_t)((wm * 32 + mf * 16 + (lane & 15)) * (LDA * 2))
               + (uint32_t)((lane >> 4) << 4);
#pragma unroll
    for (int p = 0; p < 4; p++)
        pB[p] = sbase + SM_B
              + (uint32_t)((wn * 64 + p * 16 + (lane & 7) + ((lane >> 4) << 3)) * (LDA * 2))
              + (uint32_t)((lane & 8) << 1);

    float acc[2][8][4];
#pragma unroll
    for (int mf = 0; mf < 2; mf++)
#pragma unroll
        for (int nf = 0; nf < 8; nf++)
#pragma unroll
            for (int q = 0; q < 4; q++) acc[mf][nf][q] = 0.f;

    // ---- group 0: B chunk-0 image via cp.async (17 uint4 per thread) ----
    {
        const uint4* sB = g_Bimg4;
#pragma unroll
        for (int j = tid; j < 4352; j += GT)
            cpa16(sbase + SM_B + j * 16, sB + j);
    }
    cpa_commit();
    // ---- group 1: x rows (chunk 1) fp32 -> scratch via cp.async ----
    {
#pragma unroll
        for (int j = 0; j < 4096 / GT; j++) {    // 16 per thread
            int i  = tid + j * GT;
            int r  = i >> 5;
            int kq = i & 31;
            int gr = row0 + r;
            cpa16z(sbase + SM_X + (uint32_t)(r * 512 + kq * 16),
                   x + (size_t)gr * D_FEAT + kq * 4, gr < n_nodes);
        }
    }
    cpa_commit();

    // ---- stage A chunk 0 from g_h (fp32 load, split bf16 hi/lo) ----
#pragma unroll
    for (int j = 0; j < (TM * CK / 4) / GT; j++) {       // 16 iters
        int i  = tid + j * GT;
        int r  = i >> 5;
        int kq = i & 31;
        int gr = row0 + r;
        float4 v = make_float4(0.f, 0.f, 0.f, 0.f);
        if (gr < n_nodes) v = ((const float4*)(g_h + (size_t)gr * D_FEAT))[kq];
        uint32_t h01 = bf16x2(v.y, v.x);
        uint32_t h23 = bf16x2(v.w, v.z);
        float fx = __uint_as_float(h01 << 16);
        float fy = __uint_as_float(h01 & 0xffff0000u);
        float fz = __uint_as_float(h23 << 16);
        float fw = __uint_as_float(h23 & 0xffff0000u);
        uint32_t l01 = bf16x2(v.y - fy, v.x - fx);
        uint32_t l23 = bf16x2(v.w - fw, v.z - fz);
        char* dst = smem + SM_A + r * (LDA * 2) + kq * 8;
        *(uint2*)dst             = make_uint2(h01, h23);
        *(uint2*)(dst + SM_PART) = make_uint2(l01, l23);
    }
    cpa_wait<1>();        // B chunk-0 resident (scratch may still be in flight)
    __syncthreads();

    for (int c = 0; c < 2; c++) {
        // ---- MMA mainloop: 8 k-steps of 16 ----
#pragma unroll
        for (int ks = 0; ks < CK / 16; ks++) {
            const uint32_t k0b = (uint32_t)(ks << 5);
            uint32_t Ah[2][4], Al[2][4];
#pragma unroll
            for (int mf = 0; mf < 2; mf++) {
                ldsm4(Ah[mf], pA[mf] + k0b);
                ldsm4(Al[mf], pA[mf] + SM_PART + k0b);
            }
            uint32_t Bh[4][4], Bl[4][4];
#pragma unroll
            for (int p = 0; p < 4; p++) {
                ldsm4(Bh[p], pB[p] + k0b);
                ldsm4(Bl[p], pB[p] + SM_PART + k0b);
            }
#pragma unroll
            for (int mf = 0; mf < 2; mf++)
#pragma unroll
                for (int p = 0; p < 4; p++) {
                    mma_bf16(acc[mf][2 * p],     Ah[mf], Bh[p][0], Bh[p][1]);
                    mma_bf16(acc[mf][2 * p + 1], Ah[mf], Bh[p][2], Bh[p][3]);
                    mma_bf16(acc[mf][2 * p],     Al[mf], Bh[p][0], Bh[p][1]);
                    mma_bf16(acc[mf][2 * p + 1], Al[mf], Bh[p][2], Bh[p][3]);
                    mma_bf16(acc[mf][2 * p],     Ah[mf], Bl[p][0], Bl[p][1]);
                    mma_bf16(acc[mf][2 * p + 1], Ah[mf], Bl[p][2], Bl[p][3]);
                }
        }

        if (c == 0) {
            cpa_wait<0>();        // x scratch complete
            __syncthreads();      // everyone done reading A img + B0

            // ---- group: B chunk-1 image via cp.async ----
            {
                const uint4* sB = g_Bimg4 + 4352;
#pragma unroll
                for (int j = tid; j < 4352; j += GT)
                    cpa16(sbase + SM_B + j * 16, sB + j);
            }
            cpa_commit();

            // ---- stage A chunk 1 from smem scratch (LDS, convert) ----
#pragma unroll
            for (int j = 0; j < (TM * CK / 4) / GT; j++) {   // 16 iters
                int i  = tid + j * GT;
                int r  = i >> 5;
                int kq = i & 31;
                float4 v = *(const float4*)(smem + SM_X + r * 512 + kq * 16);
                uint32_t h01 = bf16x2(v.y, v.x);
                uint32_t h23 = bf16x2(v.w, v.z);
                float fx = __uint_as_float(h01 << 16);
                float fy = __uint_as_float(h01 & 0xffff0000u);
                float fz = __uint_as_float(h23 << 16);
                float fw = __uint_as_float(h23 & 0xffff0000u);
                uint32_t l01 = bf16x2(v.y - fy, v.x - fx);
                uint32_t l23 = bf16x2(v.w - fw, v.z - fz);
                char* dst = smem + SM_A + r * (LDA * 2) + kq * 8;
                *(uint2*)dst             = make_uint2(h01, h23);
                *(uint2*)(dst + SM_PART) = make_uint2(l01, l23);
            }
            cpa_wait<0>();        // B chunk-1 resident
            __syncthreads();
        }
    }

    // ---- epilogue: relu + store ----
#pragma unroll
    for (int mf = 0; mf < 2; mf++) {
        int gr0 = row0 + wm * 32 + mf * 16 + (lane >> 2);
#pragma unroll
        for (int nf = 0; nf < 8; nf++) {
            int col = wn * 64 + (nf >> 1) * 16 + (nf & 1) * 8 + (lane & 3) * 2;
            float* a = acc[mf][nf];
            if (gr0 < n_nodes) {
                float2 o0 = make_float2(fmaxf(a[0], 0.f), fmaxf(a[1], 0.f));
                *(float2*)(out + (size_t)gr0 * OUT_DIM + col) = o0;
            }
            if (gr0 + 8 < n_nodes) {
                float2 o1 = make_float2(fmaxf(a[2], 0.f), fmaxf(a[3], 0.f));
                *(float2*)(out + (size_t)(gr0 + 8) * OUT_DIM + col) = o1;
            }
        }
    }
}

// ============================== launch =====================================
extern "C" void kernel_launch(void* const* d_in, const int* in_sizes, int n_in,
                              void* d_out, int out_size) {
    const float* x    = (const float*)d_in[0];
    const int*   rows = (const int*)  d_in[1];
    const int*   cols = (const int*)  d_in[2];
    const float* vals = (const float*)d_in[3];
    const float* W    = (const float*)d_in[4];
    float*       out  = (float*)d_out;

    const int n_nodes = in_sizes[0] / D_FEAT;
    const int n_edges = in_sizes[1];
    const int nb      = (n_nodes + SCAN_BLK - 1) / SCAN_BLK;

    hist_prep_kernel<<<(n_edges + 255) / 256, 256>>>(rows, W, n_nodes, n_edges);
    scan_reduce_kernel<<<nb, 256>>>(n_nodes);
    scan_write_kernel<<<nb, SCAN_BLK>>>(n_nodes, nb, n_edges);
    scatter_kernel<<<(n_edges + 255) / 256, 256>>>(rows, cols, vals, n_edges);

    long long spmm_threads = (long long)n_nodes * 32;
    spmm_csr_kernel<<<(int)((spmm_threads + 255) / 256), 256>>>(x, n_nodes);

    cudaFuncSetAttribute(gemm_mma_kernel,
                         cudaFuncAttributeMaxDynamicSharedMemorySize, SM_TOTAL);
    gemm_mma_kernel<<<(n_nodes + TM - 1) / TM, GT, SM_TOTAL>>>(x, out, n_nodes);
}